// round 15
// baseline (speedup 1.0000x reference)
#include <cuda_runtime.h>
#include <cuda_fp16.h>
#include <math.h>
#include <stdint.h>

#define B_   4
#define S_   4096
#define E_   2048
#define NH_  16
#define HD_  128
#define MTOT (B_ * S_)       /* 16384 */
#define NHEADS (B_ * NH_)    /* 64 */
#define KSPLIT 4

typedef __half h16;

// ---------------- scratch (device globals; no runtime allocation) ----------------
__device__ h16   g_x  [(size_t)MTOT * E_];
__device__ h16   g_wq [(size_t)E_ * E_],   g_wk [(size_t)E_ * E_];
__device__ h16   g_wv [(size_t)E_ * E_],   g_wf [(size_t)E_ * E_];
__device__ h16   g_q  [(size_t)MTOT * E_];
__device__ h16   g_Kt [(size_t)NHEADS * HD_ * S_];
__device__ h16   g_Vt [(size_t)NHEADS * HD_ * S_];
__device__ float g_kkp [KSPLIT * NHEADS * HD_ * HD_];
__device__ float g_ktvp[KSPLIT * NHEADS * HD_ * HD_];
__device__ h16   g_s  [NHEADS * HD_ * HD_];            // score row-major [d][e]
__device__ h16   g_w2 [(size_t)B_ * E_ * E_];          // per-batch fused weight [n][k=(h,d)]

// =========================== helpers ==============================================
__device__ __forceinline__ uint32_t smem_u32(const void* p) {
    return (uint32_t)__cvta_generic_to_shared(p);
}
__device__ __forceinline__ uint32_t pack2h(h16 a, h16 b) {
    return (uint32_t)__half_as_ushort(a) | ((uint32_t)__half_as_ushort(b) << 16);
}

#define CP_COMMIT() asm volatile("cp.async.commit_group;" ::: "memory")
#define CP_WAIT(n)  asm volatile("cp.async.wait_group %0;" :: "n"(n) : "memory")

__device__ __forceinline__ void cpa16(uint32_t s, const void* g) {
    asm volatile("cp.async.cg.shared.global [%0], [%1], 16;" :: "r"(s), "l"(g));
}
__device__ __forceinline__ void ldsm4(uint32_t (&r)[4], uint32_t a) {
    asm volatile("ldmatrix.sync.aligned.m8n8.x4.shared.b16 {%0,%1,%2,%3}, [%4];"
                 : "=r"(r[0]), "=r"(r[1]), "=r"(r[2]), "=r"(r[3]) : "r"(a));
}
__device__ __forceinline__ void mma_f16(float (&c)[4], const uint32_t (&a)[4],
                                        uint32_t b0, uint32_t b1) {
    asm volatile("mma.sync.aligned.m16n8k16.row.col.f32.f16.f16.f32 "
        "{%0,%1,%2,%3}, {%4,%5,%6,%7}, {%8,%9}, {%0,%1,%2,%3};"
        : "+f"(c[0]), "+f"(c[1]), "+f"(c[2]), "+f"(c[3])
        : "r"(a[0]), "r"(a[1]), "r"(a[2]), "r"(a[3]), "r"(b0), "r"(b1));
}
__device__ __forceinline__ uint32_t swz(uint32_t row, uint32_t cb) {
    return row * 128 + (cb ^ ((row & 7) << 4));
}

#define ACC_INIT(acc) \
    _Pragma("unroll") for (int a_ = 0; a_ < 4; a_++) \
    _Pragma("unroll") for (int b_ = 0; b_ < 4; b_++) \
    _Pragma("unroll") for (int c_ = 0; c_ < 4; c_++) acc[a_][b_][c_] = 0.f;

// =========================== MI=4 GEMM machinery (all kernels) ====================
// Block tile 128(M) x 128(N) x 64(K); 8 warps 2(M) x 4(N); warp tile 64x32.
// Stage = A 16KB | B 16KB = 32KB; 2-stage double buffer = 64KB -> 2 blocks/SM.
#define STG 32768

__device__ __forceinline__ void load_tile128(uint32_t sbase, const h16* g, int ldg, int tid) {
    #pragma unroll
    for (int t = 0; t < 4; t++) {
        int idx = tid + t * 256;
        int r = idx >> 3, c = idx & 7;
        cpa16(sbase + swz(r, c * 16), g + (size_t)r * ldg + c * 8);
    }
}
__device__ __forceinline__ void stage_load(uint32_t sbase,
    const h16* A, int lda, const h16* Bs, int ldb, int tid)
{
    load_tile128(sbase,          A,  lda, tid);
    load_tile128(sbase + 16384,  Bs, ldb, tid);
}
__device__ __forceinline__ void compute_stage(uint32_t sbase, int wm, int wn, int lane,
                                              float (&acc)[4][4][4])
{
    const uint32_t sA = sbase, sB = sbase + 16384;
    const int arow = wm * 64 + (lane & 15);
    const uint32_t acbx = (lane & 16) ? 16 : 0;
    const int brow = wn * 32 + (lane & 7) + ((lane & 16) ? 8 : 0);
    const uint32_t bcbx = (lane & 8) ? 16 : 0;

    #pragma unroll
    for (int kk = 0; kk < 4; kk++) {
        const uint32_t acb = kk * 32 + acbx, bcb = kk * 32 + bcbx;
        uint32_t bb[2][4];
        #pragma unroll
        for (int nj2 = 0; nj2 < 2; nj2++)
            ldsm4(bb[nj2], sB + swz(brow + nj2 * 16, bcb));
        #pragma unroll
        for (int mi = 0; mi < 4; mi++) {
            uint32_t aa[4];
            ldsm4(aa, sA + swz(arow + mi * 16, acb));
            #pragma unroll
            for (int nj = 0; nj < 4; nj++) {
                const int j2 = nj >> 1, jo = (nj & 1) * 2;
                mma_f16(acc[mi][nj], aa, bb[j2][jo], bb[j2][jo + 1]);
            }
        }
    }
}
// double-buffered mainloop (prefetch depth 1)
__device__ __forceinline__ void run_mainloop_db(uint32_t sm,
    const h16* pA, int lda, const h16* pB, int ldb, int KT,
    int wm, int wn, int lane, int tid, float (&acc)[4][4][4])
{
    stage_load(sm, pA, lda, pB, ldb, tid);
    CP_COMMIT();
    for (int i = 0; i < KT; i++) {
        if (i + 1 < KT) {
            const int k0 = (i + 1) * 64;
            stage_load(sm + ((i + 1) & 1) * STG, pA + k0, lda, pB + k0, ldb, tid);
            CP_COMMIT();
            CP_WAIT(1);
        } else {
            CP_WAIT(0);
        }
        __syncthreads();
        compute_stage(sm + (i & 1) * STG, wm, wn, lane, acc);
        __syncthreads();
    }
}

// =========================== conversion kernels ===================================
__global__ void conv_h_kernel(const float* __restrict__ in) {
    size_t i = ((size_t)blockIdx.x * 256 + threadIdx.x) * 4;
    float4 v = *(const float4*)(in + i);
    *(uint2*)(g_x + i) = make_uint2(
        pack2h(__float2half_rn(v.x), __float2half_rn(v.y)),
        pack2h(__float2half_rn(v.z), __float2half_rn(v.w)));
}
__global__ void conv_T_kernel(const float* __restrict__ W0, const float* __restrict__ W1,
                              const float* __restrict__ W2, const float* __restrict__ W3) {
    __shared__ float t[32][33];
    const int z = blockIdx.z;
    const float* W = (z == 0) ? W0 : (z == 1) ? W1 : (z == 2) ? W2 : W3;
    h16* wt = (z == 0) ? g_wq : (z == 1) ? g_wk : (z == 2) ? g_wv : g_wf;
    const int n0 = blockIdx.x * 32, k0 = blockIdx.y * 32;
    const int tx = threadIdx.x, ty = threadIdx.y;
    #pragma unroll
    for (int j = 0; j < 4; j++)
        t[ty + 8 * j][tx] = W[(size_t)(k0 + ty + 8 * j) * E_ + n0 + tx];
    __syncthreads();
    #pragma unroll
    for (int j = 0; j < 4; j++)
        wt[(size_t)(n0 + ty + 8 * j) * E_ + k0 + tx] = __float2half_rn(t[tx][ty + 8 * j]);
}

// =========================== fused QKV GEMM (128x128, 2 blk/SM) ===================
// z=0: Q -> row-major fp16; z=1: K -> transposed fp16; z=2: V -> transposed fp16
__global__ __launch_bounds__(256, 2) void gemm_qkv(
    const float* __restrict__ bq, const float* __restrict__ bk,
    const float* __restrict__ bv)
{
    extern __shared__ char smraw[];
    const uint32_t sm = (smem_u32(smraw) + 127) & ~127u;
    const int tid = threadIdx.x, lane = tid & 31, wid = tid >> 5;
    const int wm = wid >> 2, wn = wid & 3;
    const int m0 = blockIdx.y * 128, n0 = blockIdx.x * 128;
    const int z = blockIdx.z;

    const h16* Bp = (z == 0) ? g_wq : (z == 1) ? g_wk : g_wv;
    const float* bias = (z == 0) ? bq : (z == 1) ? bk : bv;

    float acc[4][4][4];
    ACC_INIT(acc)

    run_mainloop_db(sm, g_x + (size_t)m0 * E_, E_, Bp + (size_t)n0 * E_, E_,
                    E_ / 64, wm, wn, lane, tid, acc);

    const int rb = wm * 64 + (lane >> 2);
    const int cb = wn * 32 + (lane & 3) * 2;

    if (z == 0) {
        #pragma unroll
        for (int mi = 0; mi < 4; mi++)
            #pragma unroll
            for (int nj = 0; nj < 4; nj++) {
                const int r = m0 + rb + mi * 16;
                const int c = n0 + cb + nj * 8;
                const float b0 = bias[c], b1 = bias[c + 1];
                *(uint32_t*)(g_q + (size_t)r * E_ + c) =
                    pack2h(__float2half_rn(acc[mi][nj][0] + b0),
                           __float2half_rn(acc[mi][nj][1] + b1));
                *(uint32_t*)(g_q + (size_t)(r + 8) * E_ + c) =
                    pack2h(__float2half_rn(acc[mi][nj][2] + b0),
                           __float2half_rn(acc[mi][nj][3] + b1));
            }
        return;
    }

    // transposed epilogue via fp16 smem bounce: [128 s][132 pitch] halves
    __syncthreads();
    h16* sT = (h16*)(smraw) + 64;
    #pragma unroll
    for (int mi = 0; mi < 4; mi++)
        #pragma unroll
        for (int nj = 0; nj < 4; nj++) {
            const int r = rb + mi * 16;
            const int c = cb + nj * 8;
            const float b0 = bias[n0 + c], b1 = bias[n0 + c + 1];
            sT[r * 132 + c]           = __float2half_rn(acc[mi][nj][0] + b0);
            sT[r * 132 + c + 1]       = __float2half_rn(acc[mi][nj][1] + b1);
            sT[(r + 8) * 132 + c]     = __float2half_rn(acc[mi][nj][2] + b0);
            sT[(r + 8) * 132 + c + 1] = __float2half_rn(acc[mi][nj][3] + b1);
        }
    __syncthreads();

    h16* dst = (z == 1) ? g_Kt : g_Vt;
    const int e = tid >> 1, sh = (tid & 1) * 64;
    const int bB = m0 / S_, sInB = (m0 % S_) + sh;
    const size_t grow = ((size_t)(bB * E_ + n0 + e)) * S_ + sInB;

    uint32_t hw[32];
    #pragma unroll
    for (int q = 0; q < 32; q++)
        hw[q] = pack2h(sT[(sh + 2 * q) * 132 + e], sT[(sh + 2 * q + 1) * 132 + e]);
    #pragma unroll
    for (int q = 0; q < 8; q++)
        *(uint4*)(dst + grow + q * 8) = make_uint4(hw[q*4], hw[q*4+1], hw[q*4+2], hw[q*4+3]);
}

// =========================== K^T K / K^T V (split-K x4) ===========================
__global__ __launch_bounds__(256, 2) void ktk_mma()
{
    extern __shared__ char smraw[];
    const uint32_t sm = (smem_u32(smraw) + 127) & ~127u;
    const int tid = threadIdx.x, lane = tid & 31, wid = tid >> 5;
    const int wm = wid >> 2, wn = wid & 3;
    const int head = blockIdx.x, which = blockIdx.y, ks = blockIdx.z;

    const size_t hb = (size_t)head * HD_ * S_ + ks * (S_ / KSPLIT);
    const h16* pA = g_Kt + hb;
    const h16* pB = (which ? g_Vt : g_Kt) + hb;
    float* out = (which ? g_ktvp : g_kkp) + ((size_t)ks * NHEADS + head) * HD_ * HD_;

    float acc[4][4][4];
    ACC_INIT(acc)

    run_mainloop_db(sm, pA, S_, pB, S_, (S_ / KSPLIT) / 64, wm, wn, lane, tid, acc);

    const int row_base = wm * 64 + (lane >> 2);
    const int col_base = wn * 32 + (lane & 3) * 2;
    #pragma unroll
    for (int mi = 0; mi < 4; mi++)
        #pragma unroll
        for (int nj = 0; nj < 4; nj++) {
            const int r = row_base + mi * 16;
            const int c = col_base + nj * 8;
            *(float2*)(out + (size_t)r * HD_ + c) =
                make_float2(acc[mi][nj][0], acc[mi][nj][1]);
            *(float2*)(out + (size_t)(r + 8) * HD_ + c) =
                make_float2(acc[mi][nj][2], acc[mi][nj][3]);
        }
}

// =========================== solve + softmax (fp32 SIMT) ==========================
#define LDAUG 257
__global__ __launch_bounds__(256) void solve_softmax_kernel(const float* __restrict__ alpha)
{
    extern __shared__ float sAug[];
    __shared__ float facs[128];
    const int head = blockIdx.x;
    const int tid = threadIdx.x;
    const size_t hoff = (size_t)head * HD_ * HD_;
    const size_t pstride = (size_t)NHEADS * HD_ * HD_;
    const float a = alpha[0];

    for (int idx = tid; idx < HD_ * HD_; idx += 256) {
        int r = idx >> 7, c = idx & 127;
        float skk  = g_kkp [hoff + idx] + g_kkp [pstride + hoff + idx]
                   + g_kkp [2 * pstride + hoff + idx] + g_kkp [3 * pstride + hoff + idx];
        float sktv = g_ktvp[hoff + idx] + g_ktvp[pstride + hoff + idx]
                   + g_ktvp[2 * pstride + hoff + idx] + g_ktvp[3 * pstride + hoff + idx];
        sAug[r * LDAUG + c]       = skk + (r == c ? a : 0.f);
        sAug[r * LDAUG + 128 + c] = sktv;
    }
    __syncthreads();

    for (int k = 0; k < HD_; k++) {
        if (tid < 128) facs[tid] = sAug[tid * LDAUG + k];
        __syncthreads();
        float pivc = sAug[k * LDAUG + tid] / facs[k];
        sAug[k * LDAUG + tid] = pivc;
        __syncthreads();
        #pragma unroll 4
        for (int r = 0; r < HD_; r++)
            if (r != k) sAug[r * LDAUG + tid] -= facs[r] * pivc;
        __syncthreads();
    }

    const int warp = tid >> 5, lane = tid & 31;
    for (int r = warp; r < HD_; r += 8) {
        float vals[4];
        float mx = -1e30f;
        #pragma unroll
        for (int t = 0; t < 4; t++) {
            vals[t] = sAug[r * LDAUG + 128 + lane + 32 * t];
            mx = fmaxf(mx, vals[t]);
        }
        #pragma unroll
        for (int o = 16; o; o >>= 1) mx = fmaxf(mx, __shfl_xor_sync(0xffffffffu, mx, o));
        float sum = 0.f;
        #pragma unroll
        for (int t = 0; t < 4; t++) { vals[t] = expf(vals[t] - mx); sum += vals[t]; }
        #pragma unroll
        for (int o = 16; o; o >>= 1) sum += __shfl_xor_sync(0xffffffffu, sum, o);
        float inv = 1.f / sum;
        #pragma unroll
        for (int t = 0; t < 4; t++) {
            int e = lane + 32 * t;
            g_s[hoff + r * HD_ + e] = __float2half_rn(vals[t] * inv);  // row-major [d][e]
        }
    }
}

// =========================== W2_b = score_{b,h} @ Wfc_h slice =====================
// grid (16 n-tiles, 64 heads).  head = b*16 + h.
// D[d(128)][n(128)] = sum_e score[d][e] * Wfc[h*128+e][n]
// writes transposed into per-batch fused weight: g_w2[b][n0+n][h*128+d]
__global__ __launch_bounds__(256, 2) void w2_mma()
{
    extern __shared__ char smraw[];
    const uint32_t sm = (smem_u32(smraw) + 127) & ~127u;
    const int tid = threadIdx.x, lane = tid & 31, wid = tid >> 5;
    const int wm = wid >> 2, wn = wid & 3;
    const int n0 = blockIdx.x * 128, head = blockIdx.y;
    const int b = head >> 4, h = head & 15;

    const h16* pA = g_s + (size_t)head * HD_ * HD_;          // [d][e] lda=128
    const h16* pB = g_wf + (size_t)n0 * E_ + h * 128;        // [n][k=e slice] ldb=E_

    float acc[4][4][4];
    ACC_INIT(acc)

    run_mainloop_db(sm, pA, HD_, pB, E_, HD_ / 64, wm, wn, lane, tid, acc);

    // bounce [d][n] fp16, pitch 132
    __syncthreads();
    h16* sT = (h16*)(smraw) + 64;
    const int rb = wm * 64 + (lane >> 2);
    const int cb = wn * 32 + (lane & 3) * 2;
    #pragma unroll
    for (int mi = 0; mi < 4; mi++)
        #pragma unroll
        for (int nj = 0; nj < 4; nj++) {
            const int r = rb + mi * 16;
            const int c = cb + nj * 8;
            sT[r * 132 + c]           = __float2half_rn(acc[mi][nj][0]);
            sT[r * 132 + c + 1]       = __float2half_rn(acc[mi][nj][1]);
            sT[(r + 8) * 132 + c]     = __float2half_rn(acc[mi][nj][2]);
            sT[(r + 8) * 132 + c + 1] = __float2half_rn(acc[mi][nj][3]);
        }
    __syncthreads();

    const int n = tid >> 1, dh = (tid & 1) * 64;
    uint32_t hw[32];
    #pragma unroll
    for (int q = 0; q < 32; q++)
        hw[q] = pack2h(sT[(dh + 2 * q) * 132 + n], sT[(dh + 2 * q + 1) * 132 + n]);
    h16* dst = g_w2 + (size_t)b * E_ * E_ + (size_t)(n0 + n) * E_ + h * 128 + dh;
    #pragma unroll
    for (int q = 0; q < 8; q++)
        *(uint4*)(dst + q * 8) = make_uint4(hw[q*4], hw[q*4+1], hw[q*4+2], hw[q*4+3]);
}

// =========================== final GEMM: out = Q @ W2_b + bfc =====================
__global__ __launch_bounds__(256, 2) void gemm_fc(const float* __restrict__ bias,
                                                  float* __restrict__ outF)
{
    extern __shared__ char smraw[];
    const uint32_t sm = (smem_u32(smraw) + 127) & ~127u;
    const int tid = threadIdx.x, lane = tid & 31, wid = tid >> 5;
    const int wm = wid >> 2, wn = wid & 3;
    const int m0 = blockIdx.y * 128, n0 = blockIdx.x * 128;
    const int bB = m0 / S_;

    float acc[4][4][4];
    ACC_INIT(acc)

    run_mainloop_db(sm, g_q + (size_t)m0 * E_, E_,
                    g_w2 + (size_t)bB * E_ * E_ + (size_t)n0 * E_, E_,
                    E_ / 64, wm, wn, lane, tid, acc);

    const int row_base = m0 + wm * 64 + (lane >> 2);
    const int col_base = n0 + wn * 32 + (lane & 3) * 2;
    #pragma unroll
    for (int mi = 0; mi < 4; mi++)
        #pragma unroll
        for (int nj = 0; nj < 4; nj++) {
            const int r = row_base + mi * 16;
            const int c = col_base + nj * 8;
            const float b0 = bias[c], b1 = bias[c + 1];
            *(float2*)(outF + (size_t)r * E_ + c) =
                make_float2(acc[mi][nj][0] + b0, acc[mi][nj][1] + b1);
            *(float2*)(outF + (size_t)(r + 8) * E_ + c) =
                make_float2(acc[mi][nj][2] + b0, acc[mi][nj][3] + b1);
        }
}

// =================================================================================
extern "C" void kernel_launch(void* const* d_in, const int* in_sizes, int n_in,
                              void* d_out, int out_size)
{
    (void)in_sizes; (void)n_in; (void)out_size;
    const float* x     = (const float*)d_in[0];
    const float* alpha = (const float*)d_in[1];
    const float* Wq    = (const float*)d_in[2];
    const float* bq    = (const float*)d_in[3];
    const float* Wk    = (const float*)d_in[4];
    const float* bk    = (const float*)d_in[5];
    const float* Wv    = (const float*)d_in[6];
    const float* bv    = (const float*)d_in[7];
    const float* Wfc   = (const float*)d_in[8];
    const float* bfc   = (const float*)d_in[9];
    float* out = (float*)d_out;

    const int SMEM_G = 2 * STG + 1024;     // 66560 -> 2 blocks/SM
    const int SMEM_S = 128 * LDAUG * 4;    // 131584
    cudaFuncSetAttribute(gemm_qkv, cudaFuncAttributeMaxDynamicSharedMemorySize, SMEM_G);
    cudaFuncSetAttribute(ktk_mma,  cudaFuncAttributeMaxDynamicSharedMemorySize, SMEM_G);
    cudaFuncSetAttribute(w2_mma,   cudaFuncAttributeMaxDynamicSharedMemorySize, SMEM_G);
    cudaFuncSetAttribute(gemm_fc,  cudaFuncAttributeMaxDynamicSharedMemorySize, SMEM_G);
    cudaFuncSetAttribute(solve_softmax_kernel, cudaFuncAttributeMaxDynamicSharedMemorySize, SMEM_S);

    // 1) x -> fp16
    conv_h_kernel<<<(int)((size_t)MTOT * E_ / 4 / 256), 256>>>(x);
    // 2) transpose weights -> [N x K] fp16
    dim3 tb(32, 8), tg(E_ / 32, E_ / 32, 4);
    conv_T_kernel<<<tg, tb>>>(Wq, Wk, Wv, Wfc);
    // 3) fused Q/K/V projections (K,V written transposed directly)
    gemm_qkv<<<dim3(E_ / 128, MTOT / 128, 3), 256, SMEM_G>>>(bq, bk, bv);
    // 4) K^T K and K^T V (split-K x4 into partials)
    ktk_mma<<<dim3(NHEADS, 2, KSPLIT), 256, SMEM_G>>>();
    // 5) solve + softmax -> score row-major fp16
    solve_softmax_kernel<<<NHEADS, 256, SMEM_S>>>(alpha);
    // 6) W2_b = score @ Wfc slice, per (batch,head), transposed into g_w2
    w2_mma<<<dim3(E_ / 128, NHEADS), 256, SMEM_G>>>();
    // 7) out = Q @ W2_b + bfc
    gemm_fc<<<dim3(E_ / 128, MTOT / 128), 256, SMEM_G>>>(bfc, out);
}